// round 8
// baseline (speedup 1.0000x reference)
#include <cuda_runtime.h>
#include <cuda_bf16.h>

// FocalLoss restructured (R4 winner) + 8 pixels/thread for MLP:
//   t=0 common term: f0(x) = x^2 * (relu(x) + sp(x)),  sp = log1p(exp(-|x|))
//   label-channel correction: f1(xL) - f0(xL),  f1(x) = (1-x)^2 * (relu(-x) + sp(x))
//   loss = ALPHA * mean of V * (sum_c f0 + corr)
// N=4, C=19, H=W=512. Labels int32 (JAX x32 default).

#define NCLS 19
#define HW_SZ (512 * 512)          // 2^18
#define PIX_TOTAL (4 * 512 * 512)  // 2^20 pixels
#define PPT 8                      // pixels per thread
#define ALPHA_F 0.25f
#define TOTAL_ELEMS ((long long)4 * NCLS * 512 * 512)

__global__ void zero_out_kernel(float* out) {
    if (threadIdx.x == 0) out[0] = 0.0f;
}

__device__ __forceinline__ float softplus_neg_abs(float x) {
    // log1p(exp(-|x|)); arg of log in (1,2], no cancellation.
    return __logf(1.0f + __expf(-fabsf(x)));
}

__global__ __launch_bounds__(256) void focal_loss_kernel(
    const float* __restrict__ x,     // [N,C,H,W]
    const int*   __restrict__ label, // [N,H,W] int32
    float* __restrict__ out)
{
    const int g  = blockIdx.x * blockDim.x + threadIdx.x;
    const int p8 = g * PPT;
    float acc = 0.0f;

    if (p8 < PIX_TOTAL) {
        const int n  = p8 >> 18;
        const int hw = p8 & (HW_SZ - 1);

        const int4 lv0 = *reinterpret_cast<const int4*>(label + p8);
        const int4 lv1 = *reinterpret_cast<const int4*>(label + p8 + 4);
        int L[PPT] = { lv0.x, lv0.y, lv0.z, lv0.w, lv1.x, lv1.y, lv1.z, lv1.w };

        const size_t base = (size_t)n * (NCLS * HW_SZ) + hw;

        // ---- uniform t=0 sum: 2 independent float4 loads per channel ----
        float S0[PPT] = {0.f,0.f,0.f,0.f,0.f,0.f,0.f,0.f};
        #pragma unroll
        for (int c = 0; c < NCLS; c++) {
            const float* xp = x + base + (size_t)c * HW_SZ;
            const float4 xa = *reinterpret_cast<const float4*>(xp);
            const float4 xb = *reinterpret_cast<const float4*>(xp + 4);
            const float xs[PPT] = { xa.x, xa.y, xa.z, xa.w, xb.x, xb.y, xb.z, xb.w };
            #pragma unroll
            for (int i = 0; i < PPT; i++) {
                const float xi = xs[i];
                const float p  = fmaxf(xi, 0.0f) + softplus_neg_abs(xi);
                S0[i] = fmaf(xi * xi, p, S0[i]);
            }
        }

        // ---- per-pixel correction at the label channel (L1/L2 hits) ----
        #pragma unroll
        for (int i = 0; i < PPT; i++) {
            const bool valid = (L[i] >= 0 && L[i] != 255);
            const int  Ls    = valid ? L[i] : 0;
            const float xl   = x[base + ((size_t)Ls << 18) + i];
            const float sp   = softplus_neg_abs(xl);
            const float omx  = 1.0f - xl;
            const float f1   = omx * omx * (fmaxf(-xl, 0.0f) + sp);
            const float f0   = xl * xl * (fmaxf(xl, 0.0f) + sp);
            const float V    = valid ? 1.0f : 0.0f;
            acc = fmaf(V, S0[i] + (f1 - f0), acc);
        }
    }

    // Warp reduction
    #pragma unroll
    for (int o = 16; o > 0; o >>= 1)
        acc += __shfl_xor_sync(0xffffffffu, acc, o);

    __shared__ float warp_sums[8];
    const int lane = threadIdx.x & 31;
    const int wid  = threadIdx.x >> 5;
    if (lane == 0) warp_sums[wid] = acc;
    __syncthreads();

    if (wid == 0) {
        float v = (lane < 8) ? warp_sums[lane] : 0.0f;
        #pragma unroll
        for (int o = 4; o > 0; o >>= 1)
            v += __shfl_xor_sync(0xffffffffu, v, o);
        if (lane == 0) {
            const float scale = ALPHA_F / (float)TOTAL_ELEMS;  // LOSS_WEIGHT=1
            atomicAdd(out, v * scale);
        }
    }
}

extern "C" void kernel_launch(void* const* d_in, const int* in_sizes, int n_in,
                              void* d_out, int out_size) {
    const float* cls_score = (const float*)d_in[0];
    const int*   label     = (const int*)d_in[1];
    float* out = (float*)d_out;

    zero_out_kernel<<<1, 32>>>(out);

    const int groups  = PIX_TOTAL / PPT;   // 131072
    const int threads = 256;
    const int blocks  = groups / threads;  // 512
    focal_loss_kernel<<<blocks, threads>>>(cls_score, label, out);
}

// round 9
// speedup vs baseline: 1.1970x; 1.1970x over previous
#include <cuda_runtime.h>
#include <cuda_bf16.h>

// FocalLoss restructured + PPT=2 for max resident parallelism:
//   t=0 common term: f0(x) = x^2 * (relu(x) + sp(x)),  sp = log1p(exp(-|x|))
//   label-channel correction: f1(xL) - f0(xL),  f1(x) = (1-x)^2 * (relu(-x) + sp(x))
//   loss = ALPHA * mean of V * (sum_c f0 + corr)
// N=4, C=19, H=W=512. Labels int32 (JAX x32 default).

#define NCLS 19
#define HW_SZ (512 * 512)          // 2^18
#define PIX_TOTAL (4 * 512 * 512)  // 2^20 pixels
#define PPT 2                      // pixels per thread
#define ALPHA_F 0.25f
#define TOTAL_ELEMS ((long long)4 * NCLS * 512 * 512)

__global__ void zero_out_kernel(float* out) {
    if (threadIdx.x == 0) out[0] = 0.0f;
}

__device__ __forceinline__ float softplus_neg_abs(float x) {
    // log1p(exp(-|x|)); arg of log in (1,2], no cancellation.
    return __logf(1.0f + __expf(-fabsf(x)));
}

__global__ __launch_bounds__(256) void focal_loss_kernel(
    const float* __restrict__ x,     // [N,C,H,W]
    const int*   __restrict__ label, // [N,H,W] int32
    float* __restrict__ out)
{
    const int g  = blockIdx.x * blockDim.x + threadIdx.x;
    const int p2 = g * PPT;
    float acc = 0.0f;

    if (p2 < PIX_TOTAL) {
        const int n  = p2 >> 18;
        const int hw = p2 & (HW_SZ - 1);

        // 2 labels in one 8B load
        const int2 lv = *reinterpret_cast<const int2*>(label + p2);
        int L[PPT] = { lv.x, lv.y };

        const size_t base = (size_t)n * (NCLS * HW_SZ) + hw;

        // ---- uniform t=0 sum over 19 channels, one float2 per channel ----
        float S0[PPT] = {0.f, 0.f};
        #pragma unroll
        for (int c = 0; c < NCLS; c++) {
            const float2 xv = *reinterpret_cast<const float2*>(x + base + (size_t)c * HW_SZ);
            const float xs[PPT] = { xv.x, xv.y };
            #pragma unroll
            for (int i = 0; i < PPT; i++) {
                const float xi = xs[i];
                const float p  = fmaxf(xi, 0.0f) + softplus_neg_abs(xi);
                S0[i] = fmaf(xi * xi, p, S0[i]);
            }
        }

        // ---- per-pixel correction at the label channel (L1/L2 hits) ----
        #pragma unroll
        for (int i = 0; i < PPT; i++) {
            const bool valid = (L[i] >= 0 && L[i] != 255);
            const int  Ls    = valid ? L[i] : 0;
            const float xl   = x[base + ((size_t)Ls << 18) + i];
            const float sp   = softplus_neg_abs(xl);
            const float omx  = 1.0f - xl;
            const float f1   = omx * omx * (fmaxf(-xl, 0.0f) + sp);
            const float f0   = xl * xl * (fmaxf(xl, 0.0f) + sp);
            const float V    = valid ? 1.0f : 0.0f;
            acc = fmaf(V, S0[i] + (f1 - f0), acc);
        }
    }

    // Warp reduction
    #pragma unroll
    for (int o = 16; o > 0; o >>= 1)
        acc += __shfl_xor_sync(0xffffffffu, acc, o);

    __shared__ float warp_sums[8];
    const int lane = threadIdx.x & 31;
    const int wid  = threadIdx.x >> 5;
    if (lane == 0) warp_sums[wid] = acc;
    __syncthreads();

    if (wid == 0) {
        float v = (lane < 8) ? warp_sums[lane] : 0.0f;
        #pragma unroll
        for (int o = 4; o > 0; o >>= 1)
            v += __shfl_xor_sync(0xffffffffu, v, o);
        if (lane == 0) {
            const float scale = ALPHA_F / (float)TOTAL_ELEMS;  // LOSS_WEIGHT=1
            atomicAdd(out, v * scale);
        }
    }
}

extern "C" void kernel_launch(void* const* d_in, const int* in_sizes, int n_in,
                              void* d_out, int out_size) {
    const float* cls_score = (const float*)d_in[0];
    const int*   label     = (const int*)d_in[1];
    float* out = (float*)d_out;

    zero_out_kernel<<<1, 32>>>(out);

    const int groups  = PIX_TOTAL / PPT;   // 524288
    const int threads = 256;
    const int blocks  = groups / threads;  // 2048
    focal_loss_kernel<<<blocks, threads>>>(cls_score, label, out);
}

// round 12
// speedup vs baseline: 1.2177x; 1.0172x over previous
#include <cuda_runtime.h>
#include <cuda_bf16.h>

// FocalLoss restructured, PPT=2 body (R9 winner) + persistent grid-stride
// schedule at exactly 8 CTAs/SM (single wave, no tail quantization).
//   t=0 common term: f0(x) = x^2 * (relu(x) + sp(x)),  sp = log1p(exp(-|x|))
//   label-channel correction: f1(xL) - f0(xL),  f1(x) = (1-x)^2 * (relu(-x) + sp(x))
//   loss = ALPHA * mean of V * (sum_c f0 + corr)
// N=4, C=19, H=W=512. Labels int32 (JAX x32 default).

#define NCLS 19
#define HW_SZ (512 * 512)          // 2^18
#define PIX_TOTAL (4 * 512 * 512)  // 2^20 pixels
#define PPT 2                      // pixels per group
#define NGROUPS (PIX_TOTAL / PPT)  // 524288
#define ALPHA_F 0.25f
#define TOTAL_ELEMS ((long long)4 * NCLS * 512 * 512)
#define NUM_SMS 148
#define CTAS_PER_SM 8
#define NBLOCKS (NUM_SMS * CTAS_PER_SM)  // 1184

__global__ void zero_out_kernel(float* out) {
    if (threadIdx.x == 0) out[0] = 0.0f;
}

__device__ __forceinline__ float softplus_neg_abs(float x) {
    // log1p(exp(-|x|)); arg of log in (1,2], no cancellation.
    return __logf(1.0f + __expf(-fabsf(x)));
}

__global__ __launch_bounds__(256) void focal_loss_kernel(
    const float* __restrict__ x,     // [N,C,H,W]
    const int*   __restrict__ label, // [N,H,W] int32
    float* __restrict__ out)
{
    const int tid0    = blockIdx.x * blockDim.x + threadIdx.x;
    const int nthread = gridDim.x * blockDim.x;   // 303104
    float acc = 0.0f;

    for (int g = tid0; g < NGROUPS; g += nthread) {
        const int p2 = g * PPT;
        const int n  = p2 >> 18;
        const int hw = p2 & (HW_SZ - 1);

        const int2 lv = *reinterpret_cast<const int2*>(label + p2);
        const int L[PPT] = { lv.x, lv.y };

        const size_t base = (size_t)n * (NCLS * HW_SZ) + hw;

        // ---- uniform t=0 sum over 19 channels, one float2 per channel ----
        float S0[PPT] = {0.f, 0.f};
        #pragma unroll
        for (int c = 0; c < NCLS; c++) {
            const float2 xv = *reinterpret_cast<const float2*>(x + base + (size_t)c * HW_SZ);
            const float xs[PPT] = { xv.x, xv.y };
            #pragma unroll
            for (int i = 0; i < PPT; i++) {
                const float xi = xs[i];
                const float p  = fmaxf(xi, 0.0f) + softplus_neg_abs(xi);
                S0[i] = fmaf(xi * xi, p, S0[i]);
            }
        }

        // ---- per-pixel correction at the label channel (L1/L2 hits) ----
        #pragma unroll
        for (int i = 0; i < PPT; i++) {
            const bool valid = (L[i] >= 0 && L[i] != 255);
            const int  Ls    = valid ? L[i] : 0;
            const float xl   = x[base + ((size_t)Ls << 18) + i];
            const float sp   = softplus_neg_abs(xl);
            const float omx  = 1.0f - xl;
            const float f1   = omx * omx * (fmaxf(-xl, 0.0f) + sp);
            const float f0   = xl * xl * (fmaxf(xl, 0.0f) + sp);
            const float V    = valid ? 1.0f : 0.0f;
            acc = fmaf(V, S0[i] + (f1 - f0), acc);
        }
    }

    // Warp reduction
    #pragma unroll
    for (int o = 16; o > 0; o >>= 1)
        acc += __shfl_xor_sync(0xffffffffu, acc, o);

    __shared__ float warp_sums[8];
    const int lane = threadIdx.x & 31;
    const int wid  = threadIdx.x >> 5;
    if (lane == 0) warp_sums[wid] = acc;
    __syncthreads();

    if (wid == 0) {
        float v = (lane < 8) ? warp_sums[lane] : 0.0f;
        #pragma unroll
        for (int o = 4; o > 0; o >>= 1)
            v += __shfl_xor_sync(0xffffffffu, v, o);
        if (lane == 0) {
            const float scale = ALPHA_F / (float)TOTAL_ELEMS;  // LOSS_WEIGHT=1
            atomicAdd(out, v * scale);
        }
    }
}

extern "C" void kernel_launch(void* const* d_in, const int* in_sizes, int n_in,
                              void* d_out, int out_size) {
    const float* cls_score = (const float*)d_in[0];
    const int*   label     = (const int*)d_in[1];
    float* out = (float*)d_out;

    zero_out_kernel<<<1, 32>>>(out);
    focal_loss_kernel<<<NBLOCKS, 256>>>(cls_score, label, out);
}